// round 14
// baseline (speedup 1.0000x reference)
#include <cuda_runtime.h>
#include <cuda_bf16.h>
#include <cuda_fp16.h>
#include <math.h>
#include <stdint.h>

#define Nv 32768
#define Dv 256
#define NEv 256
#define NQv 4
#define Kv 4096
#define TEMP_INV 10.0f
#define BETAv 0.25f
#define EPSv 1e-12f
#define F8SCALE 16.0f
#define EPI_SCALE (TEMP_INV / (F8SCALE * F8SCALE)) /* 10/256 */

#define BM 128
#define BN 128
#define NBN (Nv / BN)   /* 256 column blocks */
#define GEMM_BLKS (NBN * (Kv / BM)) /* 8192 */
#define QZ_BLKS (Nv / 16)           /* 2048 */

#define PITCHB 272                      /* bytes per smem row (256 + 16 pad) */
#define TILE8_BYTES (128 * PITCHB)      /* 34816 */
#define FSMEM (2 * TILE8_BYTES)         /* 69632 */

// ---------------- device scratch (no allocations allowed) ----------------
__device__ float g_res[(size_t)Nv * Dv];      // residual          32 MB
__device__ float g_xn[(size_t)Nv * Dv];       // normalized rows   32 MB
__device__ uint32_t g_xf8[(size_t)Nv * 64];   // e4m3 normalized    8 MB
__device__ uint32_t g_qf8[(size_t)Kv * 64];   // e4m3 queries       1 MB
__device__ float g_part[(size_t)Kv * NBN];    // sum-exp partials   4 MB
__device__ float g_pos[Kv];
__device__ float g_lo[Kv];
__device__ float g_cbT[NQv * Dv * NEv];
__device__ float g_e2[NQv * NEv];
__device__ float g_r2[Nv];
__device__ float g_ssepart[QZ_BLKS];
__device__ float g_vq[NQv];

__device__ __forceinline__ uint32_t smem_u32(const void* p) {
    uint32_t a;
    asm("{ .reg .u64 t; cvta.to.shared.u64 t, %1; cvt.u32.u64 %0, t; }" : "=r"(a) : "l"(p));
    return a;
}
__device__ __forceinline__ void ldsm_x4(uint32_t& r0, uint32_t& r1, uint32_t& r2, uint32_t& r3,
                                        uint32_t addr) {
    asm volatile("ldmatrix.sync.aligned.m8n8.x4.shared.b16 {%0,%1,%2,%3}, [%4];"
                 : "=r"(r0), "=r"(r1), "=r"(r2), "=r"(r3) : "r"(addr));
}
__device__ __forceinline__ void ldsm_x2(uint32_t& r0, uint32_t& r1, uint32_t addr) {
    asm volatile("ldmatrix.sync.aligned.m8n8.x2.shared.b16 {%0,%1}, [%2];"
                 : "=r"(r0), "=r"(r1) : "r"(addr));
}
// e4m3 inputs, f32 accumulate, K=32 per instruction
__device__ __forceinline__ void mma_fp8(float* c, const uint32_t* a, const uint32_t* b) {
    asm volatile(
        "mma.sync.aligned.m16n8k32.row.col.f32.e4m3.e4m3.f32 "
        "{%0,%1,%2,%3}, {%4,%5,%6,%7}, {%8,%9}, {%0,%1,%2,%3};"
        : "+f"(c[0]), "+f"(c[1]), "+f"(c[2]), "+f"(c[3])
        : "r"(a[0]), "r"(a[1]), "r"(a[2]), "r"(a[3]), "r"(b[0]), "r"(b[1]));
}
// pack float4*F8SCALE -> 4 x e4m3 in one u32 (byte0 = v.x)
__device__ __forceinline__ uint32_t pack_e4m3(float4 v) {
    uint16_t lo, hi;
    asm("cvt.rn.satfinite.e4m3x2.f32 %0, %1, %2;" : "=h"(lo)
        : "f"(v.y * F8SCALE), "f"(v.x * F8SCALE));
    asm("cvt.rn.satfinite.e4m3x2.f32 %0, %1, %2;" : "=h"(hi)
        : "f"(v.w * F8SCALE), "f"(v.z * F8SCALE));
    return (uint32_t)lo | ((uint32_t)hi << 16);
}

// ---------------- init: residual = x ----------------
__global__ void k_copy(const float* __restrict__ x) {
    size_t i = ((size_t)blockIdx.x * 256 + threadIdx.x) * 4;
    *(float4*)&g_res[i] = *(const float4*)&x[i];
}

// ---------------- codebook transpose ----------------
__global__ void k_prep_cb(const float* __restrict__ cb) {
    __shared__ float t[32][33];
    int qb = blockIdx.z;
    int j0 = blockIdx.x * 32, d0 = blockIdx.y * 32;
    int tx = threadIdx.x & 31, ty = threadIdx.x >> 5;
    const float* src = cb + (size_t)qb * NEv * Dv;
    float* dst = g_cbT + (size_t)qb * Dv * NEv;
#pragma unroll
    for (int i = 0; i < 32; i += 8)
        t[ty + i][tx] = src[(size_t)(j0 + ty + i) * Dv + d0 + tx];
    __syncthreads();
#pragma unroll
    for (int i = 0; i < 32; i += 8)
        dst[(size_t)(d0 + ty + i) * NEv + j0 + tx] = t[tx][ty + i];
}

// ---------------- codebook squared norms ----------------
__global__ void k_e2(const float* __restrict__ cb) {
    int gw = blockIdx.x * 8 + (threadIdx.x >> 5);
    int lane = threadIdx.x & 31;
    const float* row = cb + (size_t)gw * Dv;
    float s = 0.f;
    for (int d = lane; d < Dv; d += 32) { float v = row[d]; s = fmaf(v, v, s); }
#pragma unroll
    for (int o = 16; o; o >>= 1) s += __shfl_down_sync(~0u, s, o);
    if (!lane) g_e2[gw] = s;
}

// ---------------- row norms + normalization (fp32 + e4m3) ----------------
__global__ void k_rownorm() {
    int row = blockIdx.x * 8 + (threadIdx.x >> 5);
    int lane = threadIdx.x & 31;
    const float* r = g_res + (size_t)row * Dv;
    float4 a = *(const float4*)&r[lane * 4];
    float4 b = *(const float4*)&r[128 + lane * 4];
    float s = ((a.x * a.x + a.y * a.y) + (a.z * a.z + a.w * a.w)) +
              ((b.x * b.x + b.y * b.y) + (b.z * b.z + b.w * b.w));
#pragma unroll
    for (int o = 16; o; o >>= 1) s += __shfl_down_sync(~0u, s, o);
    s = __shfl_sync(~0u, s, 0);
    if (!lane) g_r2[row] = s;
    float inv = rsqrtf(s + EPSv);
    float4 an = make_float4(a.x * inv, a.y * inv, a.z * inv, a.w * inv);
    float4 bn = make_float4(b.x * inv, b.y * inv, b.z * inv, b.w * inv);
    *(float4*)&g_xn[(size_t)row * Dv + lane * 4] = an;
    *(float4*)&g_xn[(size_t)row * Dv + 128 + lane * 4] = bn;
    g_xf8[(size_t)row * 64 + lane] = pack_e4m3(an);
    g_xf8[(size_t)row * 64 + 32 + lane] = pack_e4m3(bn);
}

// ---------------- gather queries (e4m3) + pos (fp32) ----------------
__global__ void k_gather(const int* __restrict__ i1, const int* __restrict__ i2) {
    int k = blockIdx.x * 8 + (threadIdx.x >> 5);
    int lane = threadIdx.x & 31;
    const float* x1 = g_xn + (size_t)i1[k] * Dv;
    const float* x2 = g_xn + (size_t)i2[k] * Dv;
    float4 a1 = *(const float4*)&x1[lane * 4];
    float4 b1 = *(const float4*)&x1[128 + lane * 4];
    float4 a2 = *(const float4*)&x2[lane * 4];
    float4 b2 = *(const float4*)&x2[128 + lane * 4];
    g_qf8[(size_t)k * 64 + lane] = pack_e4m3(a1);
    g_qf8[(size_t)k * 64 + 32 + lane] = pack_e4m3(b1);
    float s = ((a1.x * a2.x + a1.y * a2.y) + (a1.z * a2.z + a1.w * a2.w)) +
              ((b1.x * b2.x + b1.y * b2.y) + (b1.z * b2.z + b1.w * b2.w));
#pragma unroll
    for (int o = 16; o; o >>= 1) s += __shfl_down_sync(~0u, s, o);
    if (!lane) g_pos[k] = s * TEMP_INV;
}

// ============ fused heterogeneous kernel: fp8 GEMM tiles + quantize blocks ====
__global__ void __launch_bounds__(256) k_fused(const float* __restrict__ cb, int qstep,
                                               float* __restrict__ out_xq,
                                               float* __restrict__ out_idx) {
    extern __shared__ char smem[];
    int tid = threadIdx.x, lane = tid & 31, w = tid >> 5;

    if (blockIdx.x < GEMM_BLKS) {
        // ---------------- GEMM path (e4m3, K=256 in one stage) ----------------
        char* smA = smem;
        char* smB = smem + TILE8_BYTES;
        int wm = w >> 2, wn = w & 3;  // warp grid 2x4 (rows 64, cols 32)
        int bn = blockIdx.x & (NBN - 1), bm = blockIdx.x >> 8;

        const uint4* srcA = (const uint4*)(g_qf8 + (size_t)bm * BM * 64);
        const uint4* srcB = (const uint4*)(g_xf8 + (size_t)bn * BN * 64);
        // stage both 128x256B tiles (16 uint4 chunks per row, pitch 272 B)
#pragma unroll
        for (int i = 0; i < 8; i++) {
            int c = i * 256 + tid;
            int row = c >> 4, col = c & 15;
            uint32_t off = (uint32_t)(row * PITCHB + col * 16);
            *(uint4*)(smA + off) = srcA[row * 16 + col];
            *(uint4*)(smB + off) = srcB[row * 16 + col];
        }
        __syncthreads();

        uint32_t baseA = smem_u32(smA);
        uint32_t baseB = smem_u32(smB);
        uint32_t aAddr = baseA + (wm * 64 + (lane & 15)) * PITCHB + (lane >> 4) * 16;
        uint32_t bAddr = baseB + (wn * 32 + (lane & 7)) * PITCHB + ((lane >> 3) & 1) * 16;

        float acc[4][4][4];
#pragma unroll
        for (int mt = 0; mt < 4; mt++)
#pragma unroll
            for (int nt = 0; nt < 4; nt++)
#pragma unroll
                for (int e = 0; e < 4; e++) acc[mt][nt][e] = 0.f;

#pragma unroll
        for (int ks = 0; ks < 8; ks++) {  // K=32 e4m3 = 32 bytes per step
            uint32_t a[4][4], b[4][2];
            uint32_t ka = aAddr + ks * 32;
            uint32_t kb = bAddr + ks * 32;
#pragma unroll
            for (int mt = 0; mt < 4; mt++)
                ldsm_x4(a[mt][0], a[mt][1], a[mt][2], a[mt][3], ka + mt * 16 * PITCHB);
#pragma unroll
            for (int nt = 0; nt < 4; nt++)
                ldsm_x2(b[nt][0], b[nt][1], kb + nt * 8 * PITCHB);
#pragma unroll
            for (int mt = 0; mt < 4; mt++)
#pragma unroll
                for (int nt = 0; nt < 4; nt++)
                    mma_fp8(acc[mt][nt], a[mt], b[nt]);
        }

        // epilogue: exp row-sums. c0/c1 = row lane/4; c2/c3 = row lane/4+8.
        float sum_lo[4], sum_hi[4];
#pragma unroll
        for (int mt = 0; mt < 4; mt++) {
            float lo = 0.f, hi = 0.f;
#pragma unroll
            for (int nt = 0; nt < 4; nt++) {
                lo += __expf(acc[mt][nt][0] * EPI_SCALE) + __expf(acc[mt][nt][1] * EPI_SCALE);
                hi += __expf(acc[mt][nt][2] * EPI_SCALE) + __expf(acc[mt][nt][3] * EPI_SCALE);
            }
#pragma unroll
            for (int o = 1; o < 4; o <<= 1) {
                lo += __shfl_xor_sync(~0u, lo, o);
                hi += __shfl_xor_sync(~0u, hi, o);
            }
            sum_lo[mt] = lo;
            sum_hi[mt] = hi;
        }
        __syncthreads();
        float* red = (float*)smem;  // [128][4], reuse post-sync
        if ((lane & 3) == 0) {
            int rb = wm * 64 + (lane >> 2);
#pragma unroll
            for (int mt = 0; mt < 4; mt++) {
                red[(rb + mt * 16) * 4 + wn] = sum_lo[mt];
                red[(rb + mt * 16 + 8) * 4 + wn] = sum_hi[mt];
            }
        }
        __syncthreads();
        if (tid < BM) {
            float s = (red[tid * 4 + 0] + red[tid * 4 + 1]) +
                      (red[tid * 4 + 2] + red[tid * 4 + 3]);
            g_part[(size_t)(bm * BM + tid) * NBN + bn] = s;
        }
        return;
    }

    // ---------------- quantize path ----------------
    float* s_r = (float*)smem;                       // 16*256 floats = 16 KB
    float* s_r2 = s_r + 16 * 256;                    // 16
    float* s_wminf = s_r2 + 16;                      // 16*8
    int* s_widx = (int*)(s_wminf + 16 * 8);          // 16*8
    int* s_idx = s_widx + 16 * 8;                    // 16
    float* s_red = (float*)(s_idx + 16);             // 256
    int qblk = blockIdx.x - GEMM_BLKS;
    int r0 = qblk * 16;
#pragma unroll
    for (int p = 0; p < 4; p++)
        *(float4*)&s_r[p * 1024 + tid * 4] =
            *(const float4*)&g_res[(size_t)r0 * Dv + p * 1024 + tid * 4];
    if (tid < 16) s_r2[tid] = g_r2[r0 + tid];
    __syncthreads();

    const float* cT = g_cbT + (size_t)qstep * Dv * NEv;  // [d][j]
    float acc[16];
#pragma unroll
    for (int r = 0; r < 16; r++) acc[r] = 0.f;
#pragma unroll 4
    for (int d = 0; d < Dv; d += 4) {
        float c0 = cT[(size_t)(d + 0) * NEv + tid];
        float c1 = cT[(size_t)(d + 1) * NEv + tid];
        float c2 = cT[(size_t)(d + 2) * NEv + tid];
        float c3 = cT[(size_t)(d + 3) * NEv + tid];
#pragma unroll
        for (int r = 0; r < 16; r++) {
            float4 v = *(float4*)&s_r[r * 256 + d];
            acc[r] += (v.x * c0 + v.y * c1) + (v.z * c2 + v.w * c3);
        }
    }
    float e2v = g_e2[qstep * NEv + tid];
#pragma unroll
    for (int r = 0; r < 16; r++) {
        // reference rounding: (r2 - 2*dot) + e2, no contraction
        float d2 = __fadd_rn(__fadd_rn(s_r2[r], -__fmul_rn(2.0f, acc[r])), e2v);
        float mv = d2;
        int mi = tid;
#pragma unroll
        for (int o = 16; o; o >>= 1) {
            float ov = __shfl_down_sync(~0u, mv, o);
            int oi = __shfl_down_sync(~0u, mi, o);
            if (ov < mv || (ov == mv && oi < mi)) { mv = ov; mi = oi; }
        }
        if (!lane) { s_wminf[r * 8 + w] = mv; s_widx[r * 8 + w] = mi; }
    }
    __syncthreads();
    if (tid < 16) {
        float mv = s_wminf[tid * 8 + 0];
        int mi = s_widx[tid * 8 + 0];
#pragma unroll
        for (int w2 = 1; w2 < 8; w2++) {
            float ov = s_wminf[tid * 8 + w2];
            int oi = s_widx[tid * 8 + w2];
            if (ov < mv || (ov == mv && oi < mi)) { mv = ov; mi = oi; }
        }
        s_idx[tid] = mi;
    }
    __syncthreads();

    const float* cbq = cb + (size_t)qstep * NEv * Dv;
    float sse = 0.f;
#pragma unroll
    for (int r = 0; r < 16; r++) {
        int row = r0 + r;
        int ci = s_idx[r];
        float e = cbq[(size_t)ci * Dv + tid];
        float rv = s_r[r * 256 + tid];
        float diff = __fsub_rn(e, rv);   // q - r
        sse = fmaf(diff, diff, sse);
        float xres = __fadd_rn(rv, diff);  // straight-through rounding
        g_res[(size_t)row * Dv + tid] = __fsub_rn(rv, xres);
        size_t oo = (size_t)row * Dv + tid;
        if (qstep == 0) out_xq[oo] = xres; else out_xq[oo] += xres;
        if (tid == 0) out_idx[(size_t)row * NQv + qstep] = (float)ci;
    }
    s_red[tid] = sse;
    __syncthreads();
#pragma unroll
    for (int o = 128; o; o >>= 1) {
        if (tid < o) s_red[tid] += s_red[tid + o];
        __syncthreads();
    }
    if (!tid) g_ssepart[qblk] = s_red[0];
}

// ---------------- lse per query ----------------
__global__ void k_lse() {
    int k = blockIdx.x * 8 + (threadIdx.x >> 5);
    int lane = threadIdx.x & 31;
    const float* p = g_part + (size_t)k * NBN;
    double s = 0.0;
#pragma unroll
    for (int i = lane; i < NBN; i += 32) s += (double)p[i];
#pragma unroll
    for (int o = 16; o; o >>= 1) s += __shfl_down_sync(~0u, s, o);
    if (!lane) g_lo[k] = (float)log(s) - g_pos[k];
}

// ---------------- mean over K -> outer loss ----------------
__global__ void k_mean_outer(float* out_ol, int q) {
    __shared__ double red[256];
    int t = threadIdx.x;
    double s = 0.0;
    for (int i = t; i < Kv; i += 256) s += (double)g_lo[i];
    red[t] = s;
    __syncthreads();
#pragma unroll
    for (int o = 128; o; o >>= 1) {
        if (t < o) red[t] += red[t + o];
        __syncthreads();
    }
    if (!t) out_ol[q] = (float)(red[0] / (double)Kv);
}

// ---------------- vq loss reduce ----------------
__global__ void k_vq_reduce(int qstep) {
    __shared__ double red[256];
    int t = threadIdx.x;
    double s = 0.0;
    for (int i = t; i < QZ_BLKS; i += 256) s += (double)g_ssepart[i];
    red[t] = s;
    __syncthreads();
#pragma unroll
    for (int o = 128; o; o >>= 1) {
        if (t < o) red[t] += red[t + o];
        __syncthreads();
    }
    if (!t) {
        float m = (float)(red[0] / ((double)Nv * (double)Dv));
        g_vq[qstep] = __fadd_rn(m, __fmul_rn(BETAv, m));
    }
}

__global__ void k_final(float* out_ml) {
    if (threadIdx.x == 0)
        out_ml[0] = ((g_vq[0] + g_vq[1]) + (g_vq[2] + g_vq[3])) * 0.25f;
}

// ---------------- launch ----------------
extern "C" void kernel_launch(void* const* d_in, const int* in_sizes, int n_in,
                              void* d_out, int out_size) {
    const float* x = (const float*)d_in[0];
    const float* cb = (const float*)d_in[1];
    const int* i1 = (const int*)d_in[2];
    const int* i2 = (const int*)d_in[3];
    float* out = (float*)d_out;
    float* out_xq = out;
    float* out_ml = out + (size_t)Nv * Dv;
    float* out_ol = out_ml + 1;
    float* out_idx = out_ol + NQv;

    cudaFuncSetAttribute(k_fused, cudaFuncAttributeMaxDynamicSharedMemorySize, FSMEM);

    k_copy<<<(Nv * Dv) / 1024, 256>>>(x);
    k_prep_cb<<<dim3(NEv / 32, Dv / 32, NQv), 256>>>(cb);
    k_e2<<<(NQv * NEv) / 8, 256>>>(cb);

    for (int q = 0; q < NQv; q++) {
        k_rownorm<<<Nv / 8, 256>>>();
        k_gather<<<Kv / 8, 256>>>(i1, i2);
        k_fused<<<GEMM_BLKS + QZ_BLKS, 256, FSMEM>>>(cb, q, out_xq, out_idx);
        k_lse<<<Kv / 8, 256>>>();
        k_mean_outer<<<1, 256>>>(out_ol, q);
        k_vq_reduce<<<1, 256>>>(q);
    }
    k_final<<<1, 1>>>(out_ml);
}

// round 15
// speedup vs baseline: 1.1838x; 1.1838x over previous
#include <cuda_runtime.h>
#include <cuda_bf16.h>
#include <cuda_fp16.h>
#include <math.h>
#include <stdint.h>

#define Nv 32768
#define Dv 256
#define NEv 256
#define NQv 4
#define Kv 4096
#define TEMP_INV 10.0f
#define BETAv 0.25f
#define EPSv 1e-12f

#define BM 128
#define BN 256
#define NBN (Nv / BN)   /* 128 column blocks */
#define GEMM_BLKS (NBN * (Kv / BM)) /* 4096 */
#define QZ_BLKS (Nv / 16)           /* 2048 */

#define SPITCH 136                        /* fp16 per smem row per K-stage */
#define ASTAGE_BYTES (128 * SPITCH * 2)   /* 34816 */
#define BSTAGE_BYTES (256 * SPITCH * 2)   /* 69632 */
#define FSMEM (ASTAGE_BYTES + BSTAGE_BYTES) /* 104448 */

// ---------------- device scratch (no allocations allowed) ----------------
__device__ float g_res[(size_t)Nv * Dv];      // residual          32 MB
__device__ float g_xn[(size_t)Nv * Dv];       // normalized rows   32 MB
__device__ uint4 g_xh4[(size_t)Nv * Dv / 8];  // fp16 normalized   16 MB
__device__ uint4 g_qh4[(size_t)Kv * Dv / 8];  // fp16 queries       2 MB
__device__ float g_part[(size_t)Kv * NBN];    // sum-exp partials   2 MB
__device__ float g_pos[Kv];
__device__ float g_lo[Kv];
__device__ float g_cbT[NQv * Dv * NEv];
__device__ float g_e2[NQv * NEv];
__device__ float g_r2[Nv];
__device__ float g_ssepart[QZ_BLKS];
__device__ float g_vq[NQv];

__device__ __forceinline__ uint32_t smem_u32(const void* p) {
    uint32_t a;
    asm("{ .reg .u64 t; cvta.to.shared.u64 t, %1; cvt.u32.u64 %0, t; }" : "=r"(a) : "l"(p));
    return a;
}
__device__ __forceinline__ void ldsm_x4(uint32_t& r0, uint32_t& r1, uint32_t& r2, uint32_t& r3,
                                        uint32_t addr) {
    asm volatile("ldmatrix.sync.aligned.m8n8.x4.shared.b16 {%0,%1,%2,%3}, [%4];"
                 : "=r"(r0), "=r"(r1), "=r"(r2), "=r"(r3) : "r"(addr));
}
__device__ __forceinline__ void ldsm_x2(uint32_t& r0, uint32_t& r1, uint32_t addr) {
    asm volatile("ldmatrix.sync.aligned.m8n8.x2.shared.b16 {%0,%1}, [%2];"
                 : "=r"(r0), "=r"(r1) : "r"(addr));
}
// f16 inputs, f16 accumulate
__device__ __forceinline__ void mma_f16(uint32_t* c, const uint32_t* a, const uint32_t* b) {
    asm volatile(
        "mma.sync.aligned.m16n8k16.row.col.f16.f16.f16.f16 "
        "{%0,%1}, {%2,%3,%4,%5}, {%6,%7}, {%0,%1};"
        : "+r"(c[0]), "+r"(c[1])
        : "r"(a[0]), "r"(a[1]), "r"(a[2]), "r"(a[3]), "r"(b[0]), "r"(b[1]));
}

// ---------------- init: residual = x ----------------
__global__ void k_copy(const float* __restrict__ x) {
    size_t i = ((size_t)blockIdx.x * 256 + threadIdx.x) * 4;
    *(float4*)&g_res[i] = *(const float4*)&x[i];
}

// ---------------- codebook transpose ----------------
__global__ void k_prep_cb(const float* __restrict__ cb) {
    __shared__ float t[32][33];
    int qb = blockIdx.z;
    int j0 = blockIdx.x * 32, d0 = blockIdx.y * 32;
    int tx = threadIdx.x & 31, ty = threadIdx.x >> 5;
    const float* src = cb + (size_t)qb * NEv * Dv;
    float* dst = g_cbT + (size_t)qb * Dv * NEv;
#pragma unroll
    for (int i = 0; i < 32; i += 8)
        t[ty + i][tx] = src[(size_t)(j0 + ty + i) * Dv + d0 + tx];
    __syncthreads();
#pragma unroll
    for (int i = 0; i < 32; i += 8)
        dst[(size_t)(d0 + ty + i) * NEv + j0 + tx] = t[tx][ty + i];
}

// ---------------- codebook squared norms ----------------
__global__ void k_e2(const float* __restrict__ cb) {
    int gw = blockIdx.x * 8 + (threadIdx.x >> 5);
    int lane = threadIdx.x & 31;
    const float* row = cb + (size_t)gw * Dv;
    float s = 0.f;
    for (int d = lane; d < Dv; d += 32) { float v = row[d]; s = fmaf(v, v, s); }
#pragma unroll
    for (int o = 16; o; o >>= 1) s += __shfl_down_sync(~0u, s, o);
    if (!lane) g_e2[gw] = s;
}

// ---------------- row norms + normalization (fp32 + fp16) ----------------
__global__ void k_rownorm() {
    int row = blockIdx.x * 8 + (threadIdx.x >> 5);
    int lane = threadIdx.x & 31;
    const float* r = g_res + (size_t)row * Dv;
    float4 a = *(const float4*)&r[lane * 4];
    float4 b = *(const float4*)&r[128 + lane * 4];
    float s = ((a.x * a.x + a.y * a.y) + (a.z * a.z + a.w * a.w)) +
              ((b.x * b.x + b.y * b.y) + (b.z * b.z + b.w * b.w));
#pragma unroll
    for (int o = 16; o; o >>= 1) s += __shfl_down_sync(~0u, s, o);
    s = __shfl_sync(~0u, s, 0);
    if (!lane) g_r2[row] = s;
    float inv = rsqrtf(s + EPSv);
    float4 an = make_float4(a.x * inv, a.y * inv, a.z * inv, a.w * inv);
    float4 bn = make_float4(b.x * inv, b.y * inv, b.z * inv, b.w * inv);
    *(float4*)&g_xn[(size_t)row * Dv + lane * 4] = an;
    *(float4*)&g_xn[(size_t)row * Dv + 128 + lane * 4] = bn;
    __half2* xh = (__half2*)g_xh4;
    size_t hbase = (size_t)row * (Dv / 2);
    xh[hbase + lane * 2 + 0] = __floats2half2_rn(an.x, an.y);
    xh[hbase + lane * 2 + 1] = __floats2half2_rn(an.z, an.w);
    xh[hbase + 64 + lane * 2 + 0] = __floats2half2_rn(bn.x, bn.y);
    xh[hbase + 64 + lane * 2 + 1] = __floats2half2_rn(bn.z, bn.w);
}

// ---------------- gather queries (fp16) + pos (fp32) ----------------
__global__ void k_gather(const int* __restrict__ i1, const int* __restrict__ i2) {
    int k = blockIdx.x * 8 + (threadIdx.x >> 5);
    int lane = threadIdx.x & 31;
    const float* x1 = g_xn + (size_t)i1[k] * Dv;
    const float* x2 = g_xn + (size_t)i2[k] * Dv;
    float4 a1 = *(const float4*)&x1[lane * 4];
    float4 b1 = *(const float4*)&x1[128 + lane * 4];
    float4 a2 = *(const float4*)&x2[lane * 4];
    float4 b2 = *(const float4*)&x2[128 + lane * 4];
    __half2* qh = (__half2*)g_qh4;
    size_t hbase = (size_t)k * (Dv / 2);
    qh[hbase + lane * 2 + 0] = __floats2half2_rn(a1.x, a1.y);
    qh[hbase + lane * 2 + 1] = __floats2half2_rn(a1.z, a1.w);
    qh[hbase + 64 + lane * 2 + 0] = __floats2half2_rn(b1.x, b1.y);
    qh[hbase + 64 + lane * 2 + 1] = __floats2half2_rn(b1.z, b1.w);
    float s = ((a1.x * a2.x + a1.y * a2.y) + (a1.z * a2.z + a1.w * a2.w)) +
              ((b1.x * b2.x + b1.y * b2.y) + (b1.z * b2.z + b1.w * b2.w));
#pragma unroll
    for (int o = 16; o; o >>= 1) s += __shfl_down_sync(~0u, s, o);
    if (!lane) g_pos[k] = s * TEMP_INV;
}

// ============ fused heterogeneous kernel: GEMM tiles + quantize blocks ========
// blocks [0, GEMM_BLKS): 128x256 contrastive tile (warp tile 64x64, split-K)
// blocks [GEMM_BLKS, GEMM_BLKS+QZ_BLKS): VQ argmin/update for 16 rows
__global__ void __launch_bounds__(256) k_fused(const float* __restrict__ cb, int qstep,
                                               float* __restrict__ out_xq,
                                               float* __restrict__ out_idx) {
    extern __shared__ char smem[];
    int tid = threadIdx.x, lane = tid & 31, w = tid >> 5;

    if (blockIdx.x < GEMM_BLKS) {
        // ---------------- GEMM path ----------------
        char* smA = smem;
        char* smB = smem + ASTAGE_BYTES;
        int wm = w >> 2, wn = w & 3;  // warp grid 2x4 -> warp tile 64 rows x 64 cols
        int bn = blockIdx.x & (NBN - 1), bm = blockIdx.x >> 7;

        const uint4* srcA = g_qh4 + (size_t)bm * BM * (Dv / 8);
        const uint4* srcB = g_xh4 + (size_t)bn * BN * (Dv / 8);

        uint32_t baseA = smem_u32(smA);
        uint32_t baseB = smem_u32(smB);
        uint32_t aAddr = baseA + ((wm * 64 + (lane & 15)) * SPITCH + (lane >> 4) * 8) * 2;
        uint32_t bAddr = baseB + ((wn * 64 + (lane & 7)) * SPITCH + ((lane >> 3) & 1) * 8) * 2;

        uint32_t acc[4][8][2];  // f16x2 accumulators
#pragma unroll
        for (int mt = 0; mt < 4; mt++)
#pragma unroll
            for (int nt = 0; nt < 8; nt++) { acc[mt][nt][0] = 0u; acc[mt][nt][1] = 0u; }

#pragma unroll
        for (int s = 0; s < 2; s++) {
            // stage K cols [s*128, s*128+128): A 128 rows, B 256 rows
#pragma unroll
            for (int i = 0; i < 8; i++) {
                int c = i * 256 + tid;
                int row = c >> 4, col = c & 15;
                *(uint4*)(smA + row * (SPITCH * 2) + col * 16) = srcA[row * 32 + s * 16 + col];
            }
#pragma unroll
            for (int i = 0; i < 16; i++) {
                int c = i * 256 + tid;
                int row = c >> 4, col = c & 15;
                *(uint4*)(smB + row * (SPITCH * 2) + col * 16) = srcB[row * 32 + s * 16 + col];
            }
            __syncthreads();
#pragma unroll
            for (int ks = 0; ks < 8; ks++) {
                uint32_t a[4][4], b[8][2];
                uint32_t ka = aAddr + ks * 32;  // 16 fp16 = 32 bytes
                uint32_t kb = bAddr + ks * 32;
#pragma unroll
                for (int mt = 0; mt < 4; mt++)
                    ldsm_x4(a[mt][0], a[mt][1], a[mt][2], a[mt][3],
                            ka + mt * 16 * SPITCH * 2);
#pragma unroll
                for (int nt = 0; nt < 8; nt++)
                    ldsm_x2(b[nt][0], b[nt][1], kb + nt * 8 * SPITCH * 2);
#pragma unroll
                for (int mt = 0; mt < 4; mt++)
#pragma unroll
                    for (int nt = 0; nt < 8; nt++)
                        mma_f16(acc[mt][nt], a[mt], b[nt]);
            }
            __syncthreads();
        }

        // epilogue: exp row-sums. c0 = row lane/4, c1 = row lane/4+8.
        float sum_lo[4], sum_hi[4];
#pragma unroll
        for (int mt = 0; mt < 4; mt++) {
            float lo = 0.f, hi = 0.f;
#pragma unroll
            for (int nt = 0; nt < 8; nt++) {
                float2 p0 = __half22float2(*(__half2*)&acc[mt][nt][0]);
                float2 p1 = __half22float2(*(__half2*)&acc[mt][nt][1]);
                lo += __expf(p0.x * TEMP_INV) + __expf(p0.y * TEMP_INV);
                hi += __expf(p1.x * TEMP_INV) + __expf(p1.y * TEMP_INV);
            }
#pragma unroll
            for (int o = 1; o < 4; o <<= 1) {
                lo += __shfl_xor_sync(~0u, lo, o);
                hi += __shfl_xor_sync(~0u, hi, o);
            }
            sum_lo[mt] = lo;
            sum_hi[mt] = hi;
        }
        float* red = (float*)smem;  // [128][4], reuse post-sync
        if ((lane & 3) == 0) {
            int rb = wm * 64 + (lane >> 2);
#pragma unroll
            for (int mt = 0; mt < 4; mt++) {
                red[(rb + mt * 16) * 4 + wn] = sum_lo[mt];
                red[(rb + mt * 16 + 8) * 4 + wn] = sum_hi[mt];
            }
        }
        __syncthreads();
        if (tid < BM) {
            float s = (red[tid * 4 + 0] + red[tid * 4 + 1]) +
                      (red[tid * 4 + 2] + red[tid * 4 + 3]);
            g_part[(size_t)(bm * BM + tid) * NBN + bn] = s;
        }
        return;
    }

    // ---------------- quantize path ----------------
    float* s_r = (float*)smem;                       // 16*256 floats = 16 KB
    float* s_r2 = s_r + 16 * 256;                    // 16
    float* s_wminf = s_r2 + 16;                      // 16*8
    int* s_widx = (int*)(s_wminf + 16 * 8);          // 16*8
    int* s_idx = s_widx + 16 * 8;                    // 16
    float* s_red = (float*)(s_idx + 16);             // 256
    int qblk = blockIdx.x - GEMM_BLKS;
    int r0 = qblk * 16;
#pragma unroll
    for (int p = 0; p < 4; p++)
        *(float4*)&s_r[p * 1024 + tid * 4] =
            *(const float4*)&g_res[(size_t)r0 * Dv + p * 1024 + tid * 4];
    if (tid < 16) s_r2[tid] = g_r2[r0 + tid];
    __syncthreads();

    // dot[r] for codebook entry j = tid, f32x2-packed along d (exact fp32 lanes)
    const float* cT = g_cbT + (size_t)qstep * Dv * NEv;  // [d][j]
    unsigned long long acc2[16];
#pragma unroll
    for (int r = 0; r < 16; r++) acc2[r] = 0ull;
#pragma unroll 4
    for (int d = 0; d < Dv; d += 4) {
        float c0 = cT[(size_t)(d + 0) * NEv + tid];
        float c1 = cT[(size_t)(d + 1) * NEv + tid];
        float c2 = cT[(size_t)(d + 2) * NEv + tid];
        float c3 = cT[(size_t)(d + 3) * NEv + tid];
        unsigned long long c01, c23;
        asm("mov.b64 %0, {%1,%2};" : "=l"(c01) : "f"(c0), "f"(c1));
        asm("mov.b64 %0, {%1,%2};" : "=l"(c23) : "f"(c2), "f"(c3));
#pragma unroll
        for (int r = 0; r < 16; r++) {
            ulonglong2 v = *(const ulonglong2*)&s_r[r * 256 + d];
            asm("fma.rn.f32x2 %0, %1, %2, %0;" : "+l"(acc2[r]) : "l"(v.x), "l"(c01));
            asm("fma.rn.f32x2 %0, %1, %2, %0;" : "+l"(acc2[r]) : "l"(v.y), "l"(c23));
        }
    }
    float e2v = g_e2[qstep * NEv + tid];
#pragma unroll
    for (int r = 0; r < 16; r++) {
        uint32_t ulo, uhi;
        asm("mov.b64 {%0,%1}, %2;" : "=r"(ulo), "=r"(uhi) : "l"(acc2[r]));
        float dot = __uint_as_float(ulo) + __uint_as_float(uhi);
        // reference rounding: (r2 - 2*dot) + e2, no contraction
        float d2 = __fadd_rn(__fadd_rn(s_r2[r], -__fmul_rn(2.0f, dot)), e2v);
        float mv = d2;
        int mi = tid;
#pragma unroll
        for (int o = 16; o; o >>= 1) {
            float ov = __shfl_down_sync(~0u, mv, o);
            int oi = __shfl_down_sync(~0u, mi, o);
            if (ov < mv || (ov == mv && oi < mi)) { mv = ov; mi = oi; }
        }
        if (!lane) { s_wminf[r * 8 + w] = mv; s_widx[r * 8 + w] = mi; }
    }
    __syncthreads();
    if (tid < 16) {
        float mv = s_wminf[tid * 8 + 0];
        int mi = s_widx[tid * 8 + 0];
#pragma unroll
        for (int w2 = 1; w2 < 8; w2++) {
            float ov = s_wminf[tid * 8 + w2];
            int oi = s_widx[tid * 8 + w2];
            if (ov < mv || (ov == mv && oi < mi)) { mv = ov; mi = oi; }
        }
        s_idx[tid] = mi;
    }
    __syncthreads();

    const float* cbq = cb + (size_t)qstep * NEv * Dv;
    float sse = 0.f;
#pragma unroll
    for (int r = 0; r < 16; r++) {
        int row = r0 + r;
        int ci = s_idx[r];
        float e = cbq[(size_t)ci * Dv + tid];
        float rv = s_r[r * 256 + tid];
        float diff = __fsub_rn(e, rv);   // q - r
        sse = fmaf(diff, diff, sse);
        float xres = __fadd_rn(rv, diff);  // straight-through rounding
        g_res[(size_t)row * Dv + tid] = __fsub_rn(rv, xres);
        size_t oo = (size_t)row * Dv + tid;
        if (qstep == 0) out_xq[oo] = xres; else out_xq[oo] += xres;
        if (tid == 0) out_idx[(size_t)row * NQv + qstep] = (float)ci;
    }
    s_red[tid] = sse;
    __syncthreads();
#pragma unroll
    for (int o = 128; o; o >>= 1) {
        if (tid < o) s_red[tid] += s_red[tid + o];
        __syncthreads();
    }
    if (!tid) g_ssepart[qblk] = s_red[0];
}

// ---------------- lse per query ----------------
__global__ void k_lse() {
    int k = blockIdx.x * 8 + (threadIdx.x >> 5);
    int lane = threadIdx.x & 31;
    const float* p = g_part + (size_t)k * NBN;
    double s = 0.0;
#pragma unroll
    for (int i = lane; i < NBN; i += 32) s += (double)p[i];
#pragma unroll
    for (int o = 16; o; o >>= 1) s += __shfl_down_sync(~0u, s, o);
    if (!lane) g_lo[k] = (float)log(s) - g_pos[k];
}

// ---------------- mean over K -> outer loss ----------------
__global__ void k_mean_outer(float* out_ol, int q) {
    __shared__ double red[256];
    int t = threadIdx.x;
    double s = 0.0;
    for (int i = t; i < Kv; i += 256) s += (double)g_lo[i];
    red[t] = s;
    __syncthreads();
#pragma unroll
    for (int o = 128; o; o >>= 1) {
        if (t < o) red[t] += red[t + o];
        __syncthreads();
    }
    if (!t) out_ol[q] = (float)(red[0] / (double)Kv);
}

// ---------------- vq loss reduce ----------------
__global__ void k_vq_reduce(int qstep) {
    __shared__ double red[256];
    int t = threadIdx.x;
    double s = 0.0;
    for (int i = t; i < QZ_BLKS; i += 256) s += (double)g_ssepart[i];
    red[t] = s;
    __syncthreads();
#pragma unroll
    for (int o = 128; o; o >>= 1) {
        if (t < o) red[t] += red[t + o];
        __syncthreads();
    }
    if (!t) {
        float m = (float)(red[0] / ((double)Nv * (double)Dv));
        g_vq[qstep] = __fadd_rn(m, __fmul_rn(BETAv, m));
    }
}

__global__ void k_final(float* out_ml) {
    if (threadIdx.x == 0)
        out_ml[0] = ((g_vq[0] + g_vq[1]) + (g_vq[2] + g_vq[3])) * 0.25f;
}

// ---------------- launch ----------------
extern "C" void kernel_launch(void* const* d_in, const int* in_sizes, int n_in,
                              void* d_out, int out_size) {
    const float* x = (const float*)d_in[0];
    const float* cb = (const float*)d_in[1];
    const int* i1 = (const int*)d_in[2];
    const int* i2 = (const int*)d_in[3];
    float* out = (float*)d_out;
    float* out_xq = out;
    float* out_ml = out + (size_t)Nv * Dv;
    float* out_ol = out_ml + 1;
    float* out_idx = out_ol + NQv;

    cudaFuncSetAttribute(k_fused, cudaFuncAttributeMaxDynamicSharedMemorySize, FSMEM);

    k_copy<<<(Nv * Dv) / 1024, 256>>>(x);
    k_prep_cb<<<dim3(NEv / 32, Dv / 32, NQv), 256>>>(cb);
    k_e2<<<(NQv * NEv) / 8, 256>>>(cb);

    for (int q = 0; q < NQv; q++) {
        k_rownorm<<<Nv / 8, 256>>>();
        k_gather<<<Kv / 8, 256>>>(i1, i2);
        k_fused<<<GEMM_BLKS + QZ_BLKS, 256, FSMEM>>>(cb, q, out_xq, out_idx);
        k_lse<<<Kv / 8, 256>>>();
        k_mean_outer<<<1, 256>>>(out_ol, q);
        k_vq_reduce<<<1, 256>>>(q);
    }
    k_final<<<1, 1>>>(out_ml);
}

// round 16
// speedup vs baseline: 1.3205x; 1.1155x over previous
#include <cuda_runtime.h>
#include <cuda_bf16.h>
#include <cuda_fp16.h>
#include <math.h>
#include <stdint.h>

#define Nv 32768
#define Dv 256
#define NEv 256
#define NQv 4
#define Kv 4096
#define TEMP_INV 10.0f
#define BETAv 0.25f
#define EPSv 1e-12f

#define BM 128
#define BN 128
#define NBN (Nv / BN)   /* 256 column blocks */
#define GEMM_BLKS (NBN * (Kv / BM)) /* 8192 */
#define QZ_BLKS (Nv / 16)           /* 2048 */

#define SPITCH 136                      /* fp16 per smem row per K-stage */
#define STAGE_BYTES (128 * SPITCH * 2)  /* 34816 */
#define FSMEM (2 * STAGE_BYTES)         /* 69632: A half + B half */

// ---------------- device scratch (no allocations allowed) ----------------
__device__ float g_res[(size_t)Nv * Dv];      // residual          32 MB
__device__ float g_xn[(size_t)Nv * Dv];       // normalized rows   32 MB
__device__ uint4 g_xh4[(size_t)Nv * Dv / 8];  // fp16 normalized   16 MB
__device__ float g_part[(size_t)Kv * NBN];    // sum-exp partials   4 MB
__device__ float g_lo[Kv];
__device__ float g_cbT[NQv * Dv * NEv];
__device__ float g_e2[NQv * NEv];
__device__ float g_r2[Nv];
__device__ float g_ssepart[QZ_BLKS];
__device__ float g_vq[NQv];

__device__ __forceinline__ uint32_t smem_u32(const void* p) {
    uint32_t a;
    asm("{ .reg .u64 t; cvta.to.shared.u64 t, %1; cvt.u32.u64 %0, t; }" : "=r"(a) : "l"(p));
    return a;
}
__device__ __forceinline__ void ldsm_x4(uint32_t& r0, uint32_t& r1, uint32_t& r2, uint32_t& r3,
                                        uint32_t addr) {
    asm volatile("ldmatrix.sync.aligned.m8n8.x4.shared.b16 {%0,%1,%2,%3}, [%4];"
                 : "=r"(r0), "=r"(r1), "=r"(r2), "=r"(r3) : "r"(addr));
}
// f16 inputs, f16 accumulate
__device__ __forceinline__ void mma_f16(uint32_t* c, const uint32_t* a, const uint32_t* b) {
    asm volatile(
        "mma.sync.aligned.m16n8k16.row.col.f16.f16.f16.f16 "
        "{%0,%1}, {%2,%3,%4,%5}, {%6,%7}, {%0,%1};"
        : "+r"(c[0]), "+r"(c[1])
        : "r"(a[0]), "r"(a[1]), "r"(a[2]), "r"(a[3]), "r"(b[0]), "r"(b[1]));
}

// ---------------- init: residual = x ----------------
__global__ void k_copy(const float* __restrict__ x) {
    size_t i = ((size_t)blockIdx.x * 256 + threadIdx.x) * 4;
    *(float4*)&g_res[i] = *(const float4*)&x[i];
}

// ---------------- codebook transpose ----------------
__global__ void k_prep_cb(const float* __restrict__ cb) {
    __shared__ float t[32][33];
    int qb = blockIdx.z;
    int j0 = blockIdx.x * 32, d0 = blockIdx.y * 32;
    int tx = threadIdx.x & 31, ty = threadIdx.x >> 5;
    const float* src = cb + (size_t)qb * NEv * Dv;
    float* dst = g_cbT + (size_t)qb * Dv * NEv;
#pragma unroll
    for (int i = 0; i < 32; i += 8)
        t[ty + i][tx] = src[(size_t)(j0 + ty + i) * Dv + d0 + tx];
    __syncthreads();
#pragma unroll
    for (int i = 0; i < 32; i += 8)
        dst[(size_t)(d0 + ty + i) * NEv + j0 + tx] = t[tx][ty + i];
}

// ---------------- codebook squared norms ----------------
__global__ void k_e2(const float* __restrict__ cb) {
    int gw = blockIdx.x * 8 + (threadIdx.x >> 5);
    int lane = threadIdx.x & 31;
    const float* row = cb + (size_t)gw * Dv;
    float s = 0.f;
    for (int d = lane; d < Dv; d += 32) { float v = row[d]; s = fmaf(v, v, s); }
#pragma unroll
    for (int o = 16; o; o >>= 1) s += __shfl_down_sync(~0u, s, o);
    if (!lane) g_e2[gw] = s;
}

// ---------------- row norms + normalization (fp32 + fp16) ----------------
__global__ void k_rownorm() {
    int row = blockIdx.x * 8 + (threadIdx.x >> 5);
    int lane = threadIdx.x & 31;
    const float* r = g_res + (size_t)row * Dv;
    float4 a = *(const float4*)&r[lane * 4];
    float4 b = *(const float4*)&r[128 + lane * 4];
    float s = ((a.x * a.x + a.y * a.y) + (a.z * a.z + a.w * a.w)) +
              ((b.x * b.x + b.y * b.y) + (b.z * b.z + b.w * b.w));
#pragma unroll
    for (int o = 16; o; o >>= 1) s += __shfl_down_sync(~0u, s, o);
    s = __shfl_sync(~0u, s, 0);
    if (!lane) g_r2[row] = s;
    float inv = rsqrtf(s + EPSv);
    float4 an = make_float4(a.x * inv, a.y * inv, a.z * inv, a.w * inv);
    float4 bn = make_float4(b.x * inv, b.y * inv, b.z * inv, b.w * inv);
    *(float4*)&g_xn[(size_t)row * Dv + lane * 4] = an;
    *(float4*)&g_xn[(size_t)row * Dv + 128 + lane * 4] = bn;
    __half2* xh = (__half2*)g_xh4;
    size_t hbase = (size_t)row * (Dv / 2);
    xh[hbase + lane * 2 + 0] = __floats2half2_rn(an.x, an.y);
    xh[hbase + lane * 2 + 1] = __floats2half2_rn(an.z, an.w);
    xh[hbase + 64 + lane * 2 + 0] = __floats2half2_rn(bn.x, bn.y);
    xh[hbase + 64 + lane * 2 + 1] = __floats2half2_rn(bn.z, bn.w);
}

// ============ fused heterogeneous kernel: GEMM tiles + quantize blocks ========
// blocks [0, GEMM_BLKS): contrastive GEMM tile (A gathered via i1 at staging)
// blocks [GEMM_BLKS, GEMM_BLKS+QZ_BLKS): VQ argmin/update for 16 rows
__global__ void __launch_bounds__(256) k_fused(const float* __restrict__ cb, int qstep,
                                               const int* __restrict__ i1g,
                                               float* __restrict__ out_xq,
                                               float* __restrict__ out_idx) {
    extern __shared__ char smem[];
    int tid = threadIdx.x, lane = tid & 31, w = tid >> 5;

    if (blockIdx.x < GEMM_BLKS) {
        // ---------------- GEMM path ----------------
        char* smA = smem;
        char* smB = smem + STAGE_BYTES;
        int wm = w >> 2, wn = w & 3;  // warp grid 2x4 (rows 64, cols 32)
        int bn = blockIdx.x & (NBN - 1), bm = blockIdx.x >> 8;

        const uint4* srcB = g_xh4 + (size_t)bn * BN * (Dv / 8);
        int qbase = bm * BM;

        uint32_t baseA = smem_u32(smA);
        uint32_t baseB = smem_u32(smB);
        uint32_t aAddr = baseA + ((wm * 64 + (lane & 15)) * SPITCH + (lane >> 4) * 8) * 2;
        // B ldmatrix.x4 source: 16 n-rows per load.
        // lanes 0-7:  rows +0..7,  k bytes +0   -> r0 (n0-7, k0-7)
        // lanes 8-15: rows +0..7,  k bytes +16  -> r1 (n0-7, k8-15)
        // lanes 16-23: rows +8..15, k bytes +0  -> r2 (n8-15, k0-7)
        // lanes 24-31: rows +8..15, k bytes +16 -> r3 (n8-15, k8-15)
        uint32_t bAddr = baseB +
            ((wn * 32 + (lane & 7) + ((lane >> 4) & 1) * 8) * SPITCH) * 2 +
            ((lane >> 3) & 1) * 16;

        uint32_t acc[4][4][2];  // f16x2 accumulators
#pragma unroll
        for (int mt = 0; mt < 4; mt++)
#pragma unroll
            for (int nt = 0; nt < 4; nt++) { acc[mt][nt][0] = 0u; acc[mt][nt][1] = 0u; }

#pragma unroll
        for (int s = 0; s < 2; s++) {
            // stage K cols [s*128, s*128+128): A gathered via i1, B direct
#pragma unroll
            for (int i = 0; i < 8; i++) {
                int c = i * 256 + tid;
                int row = c >> 4, col = c & 15;  // 16 x 16B chunks per 128-col row
                uint32_t off = (uint32_t)(row * (SPITCH * 2) + col * 16);
                int qrow = i1g[qbase + row];
                *(uint4*)(smA + off) = g_xh4[(size_t)qrow * 32 + s * 16 + col];
                *(uint4*)(smB + off) = srcB[row * 32 + s * 16 + col];
            }
            __syncthreads();
#pragma unroll
            for (int ks = 0; ks < 8; ks++) {
                uint32_t a[4][4], b[4][2];
                uint32_t ka = aAddr + ks * 32;  // 16 fp16 = 32 bytes
                uint32_t kb = bAddr + ks * 32;
#pragma unroll
                for (int mt = 0; mt < 4; mt++)
                    ldsm_x4(a[mt][0], a[mt][1], a[mt][2], a[mt][3],
                            ka + mt * 16 * SPITCH * 2);
#pragma unroll
                for (int nt2 = 0; nt2 < 2; nt2++)
                    ldsm_x4(b[nt2 * 2][0], b[nt2 * 2][1], b[nt2 * 2 + 1][0],
                            b[nt2 * 2 + 1][1], kb + nt2 * 16 * SPITCH * 2);
#pragma unroll
                for (int mt = 0; mt < 4; mt++)
#pragma unroll
                    for (int nt = 0; nt < 4; nt++)
                        mma_f16(acc[mt][nt], a[mt], b[nt]);
            }
            __syncthreads();
        }

        // epilogue: exp row-sums. c0 = row lane/4, c1 = row lane/4+8.
        float sum_lo[4], sum_hi[4];
#pragma unroll
        for (int mt = 0; mt < 4; mt++) {
            float lo = 0.f, hi = 0.f;
#pragma unroll
            for (int nt = 0; nt < 4; nt++) {
                float2 p0 = __half22float2(*(__half2*)&acc[mt][nt][0]);
                float2 p1 = __half22float2(*(__half2*)&acc[mt][nt][1]);
                lo += __expf(p0.x * TEMP_INV) + __expf(p0.y * TEMP_INV);
                hi += __expf(p1.x * TEMP_INV) + __expf(p1.y * TEMP_INV);
            }
#pragma unroll
            for (int o = 1; o < 4; o <<= 1) {
                lo += __shfl_xor_sync(~0u, lo, o);
                hi += __shfl_xor_sync(~0u, hi, o);
            }
            sum_lo[mt] = lo;
            sum_hi[mt] = hi;
        }
        float* red = (float*)smem;  // [128][4], reuse post-sync
        if ((lane & 3) == 0) {
            int rb = wm * 64 + (lane >> 2);
#pragma unroll
            for (int mt = 0; mt < 4; mt++) {
                red[(rb + mt * 16) * 4 + wn] = sum_lo[mt];
                red[(rb + mt * 16 + 8) * 4 + wn] = sum_hi[mt];
            }
        }
        __syncthreads();
        if (tid < BM) {
            float s = (red[tid * 4 + 0] + red[tid * 4 + 1]) +
                      (red[tid * 4 + 2] + red[tid * 4 + 3]);
            g_part[(size_t)(bm * BM + tid) * NBN + bn] = s;
        }
        return;
    }

    // ---------------- quantize path ----------------
    float* s_r = (float*)smem;                       // 16*256 floats = 16 KB
    float* s_r2 = s_r + 16 * 256;                    // 16
    float* s_wminf = s_r2 + 16;                      // 16*8
    int* s_widx = (int*)(s_wminf + 16 * 8);          // 16*8
    int* s_idx = s_widx + 16 * 8;                    // 16
    float* s_red = (float*)(s_idx + 16);             // 256
    int qblk = blockIdx.x - GEMM_BLKS;
    int r0 = qblk * 16;
#pragma unroll
    for (int p = 0; p < 4; p++)
        *(float4*)&s_r[p * 1024 + tid * 4] =
            *(const float4*)&g_res[(size_t)r0 * Dv + p * 1024 + tid * 4];
    if (tid < 16) s_r2[tid] = g_r2[r0 + tid];
    __syncthreads();

    const float* cT = g_cbT + (size_t)qstep * Dv * NEv;  // [d][j]
    float acc[16];
#pragma unroll
    for (int r = 0; r < 16; r++) acc[r] = 0.f;
#pragma unroll 4
    for (int d = 0; d < Dv; d += 4) {
        float c0 = cT[(size_t)(d + 0) * NEv + tid];
        float c1 = cT[(size_t)(d + 1) * NEv + tid];
        float c2 = cT[(size_t)(d + 2) * NEv + tid];
        float c3 = cT[(size_t)(d + 3) * NEv + tid];
#pragma unroll
        for (int r = 0; r < 16; r++) {
            float4 v = *(float4*)&s_r[r * 256 + d];
            acc[r] += (v.x * c0 + v.y * c1) + (v.z * c2 + v.w * c3);
        }
    }
    float e2v = g_e2[qstep * NEv + tid];
#pragma unroll
    for (int r = 0; r < 16; r++) {
        // reference rounding: (r2 - 2*dot) + e2, no contraction
        float d2 = __fadd_rn(__fadd_rn(s_r2[r], -__fmul_rn(2.0f, acc[r])), e2v);
        float mv = d2;
        int mi = tid;
#pragma unroll
        for (int o = 16; o; o >>= 1) {
            float ov = __shfl_down_sync(~0u, mv, o);
            int oi = __shfl_down_sync(~0u, mi, o);
            if (ov < mv || (ov == mv && oi < mi)) { mv = ov; mi = oi; }
        }
        if (!lane) { s_wminf[r * 8 + w] = mv; s_widx[r * 8 + w] = mi; }
    }
    __syncthreads();
    if (tid < 16) {
        float mv = s_wminf[tid * 8 + 0];
        int mi = s_widx[tid * 8 + 0];
#pragma unroll
        for (int w2 = 1; w2 < 8; w2++) {
            float ov = s_wminf[tid * 8 + w2];
            int oi = s_widx[tid * 8 + w2];
            if (ov < mv || (ov == mv && oi < mi)) { mv = ov; mi = oi; }
        }
        s_idx[tid] = mi;
    }
    __syncthreads();

    const float* cbq = cb + (size_t)qstep * NEv * Dv;
    float sse = 0.f;
#pragma unroll
    for (int r = 0; r < 16; r++) {
        int row = r0 + r;
        int ci = s_idx[r];
        float e = cbq[(size_t)ci * Dv + tid];
        float rv = s_r[r * 256 + tid];
        float diff = __fsub_rn(e, rv);   // q - r
        sse = fmaf(diff, diff, sse);
        float xres = __fadd_rn(rv, diff);  // straight-through rounding
        g_res[(size_t)row * Dv + tid] = __fsub_rn(rv, xres);
        size_t oo = (size_t)row * Dv + tid;
        if (qstep == 0) out_xq[oo] = xres; else out_xq[oo] += xres;
        if (tid == 0) out_idx[(size_t)row * NQv + qstep] = (float)ci;
    }
    s_red[tid] = sse;
    __syncthreads();
#pragma unroll
    for (int o = 128; o; o >>= 1) {
        if (tid < o) s_red[tid] += s_red[tid + o];
        __syncthreads();
    }
    if (!tid) g_ssepart[qblk] = s_red[0];
}

// ---------------- lse per query (pos computed inline) ----------------
__global__ void k_lse(const int* __restrict__ i1, const int* __restrict__ i2) {
    int k = blockIdx.x * 8 + (threadIdx.x >> 5);
    int lane = threadIdx.x & 31;
    // pos: same arithmetic as original k_gather (bit-identical)
    const float* x1 = g_xn + (size_t)i1[k] * Dv;
    const float* x2 = g_xn + (size_t)i2[k] * Dv;
    float4 a1 = *(const float4*)&x1[lane * 4];
    float4 b1 = *(const float4*)&x1[128 + lane * 4];
    float4 a2 = *(const float4*)&x2[lane * 4];
    float4 b2 = *(const float4*)&x2[128 + lane * 4];
    float ps = ((a1.x * a2.x + a1.y * a2.y) + (a1.z * a2.z + a1.w * a2.w)) +
               ((b1.x * b2.x + b1.y * b2.y) + (b1.z * b2.z + b1.w * b2.w));
#pragma unroll
    for (int o = 16; o; o >>= 1) ps += __shfl_down_sync(~0u, ps, o);

    const float* p = g_part + (size_t)k * NBN;
    double s = 0.0;
#pragma unroll
    for (int i = lane; i < NBN; i += 32) s += (double)p[i];
#pragma unroll
    for (int o = 16; o; o >>= 1) s += __shfl_down_sync(~0u, s, o);
    if (!lane) g_lo[k] = (float)log(s) - ps * TEMP_INV;
}

// ---------------- merged tail: block0 = outer mean, block1 = vq reduce -------
__global__ void k_tail(float* out_ol, int q) {
    __shared__ double red[256];
    int t = threadIdx.x;
    if (blockIdx.x == 0) {
        double s = 0.0;
        for (int i = t; i < Kv; i += 256) s += (double)g_lo[i];
        red[t] = s;
        __syncthreads();
#pragma unroll
        for (int o = 128; o; o >>= 1) {
            if (t < o) red[t] += red[t + o];
            __syncthreads();
        }
        if (!t) out_ol[q] = (float)(red[0] / (double)Kv);
    } else {
        double s = 0.0;
        for (int i = t; i < QZ_BLKS; i += 256) s += (double)g_ssepart[i];
        red[t] = s;
        __syncthreads();
#pragma unroll
        for (int o = 128; o; o >>= 1) {
            if (t < o) red[t] += red[t + o];
            __syncthreads();
        }
        if (!t) {
            float m = (float)(red[0] / ((double)Nv * (double)Dv));
            g_vq[q] = __fadd_rn(m, __fmul_rn(BETAv, m));
        }
    }
}

__global__ void k_final(float* out_ml) {
    if (threadIdx.x == 0)
        out_ml[0] = ((g_vq[0] + g_vq[1]) + (g_vq[2] + g_vq[3])) * 0.25f;
}

// ---------------- launch ----------------
extern "C" void kernel_launch(void* const* d_in, const int* in_sizes, int n_in,
                              void* d_out, int out_size) {
    const float* x = (const float*)d_in[0];
    const float* cb = (const float*)d_in[1];
    const int* i1 = (const int*)d_in[2];
    const int* i2 = (const int*)d_in[3];
    float* out = (float*)d_out;
    float* out_xq = out;
    float* out_ml = out + (size_t)Nv * Dv;
    float* out_ol = out_ml + 1;
    float* out_idx = out_ol + NQv;

    cudaFuncSetAttribute(k_fused, cudaFuncAttributeMaxDynamicSharedMemorySize, FSMEM);

    k_copy<<<(Nv * Dv) / 1024, 256>>>(x);
    k_prep_cb<<<dim3(NEv / 32, Dv / 32, NQv), 256>>>(cb);
    k_e2<<<(NQv * NEv) / 8, 256>>>(cb);

    for (int q = 0; q < NQv; q++) {
        k_rownorm<<<Nv / 8, 256>>>();
        k_fused<<<GEMM_BLKS + QZ_BLKS, 256, FSMEM>>>(cb, q, i1, out_xq, out_idx);
        k_lse<<<Kv / 8, 256>>>(i1, i2);
        k_tail<<<2, 256>>>(out_ol, q);
    }
    k_final<<<1, 1>>>(out_ml);
}

// round 17
// speedup vs baseline: 1.4020x; 1.0617x over previous
#include <cuda_runtime.h>
#include <cuda_bf16.h>
#include <cuda_fp16.h>
#include <math.h>
#include <stdint.h>

#define Nv 32768
#define Dv 256
#define NEv 256
#define NQv 4
#define Kv 4096
#define TEMP_INV 10.0f
#define BETAv 0.25f
#define EPSv 1e-12f

#define BM 128
#define BN 128
#define NBN (Nv / BN)   /* 256 column blocks */
#define GEMM_BLKS (NBN * (Kv / BM)) /* 8192 */
#define QZ_BLKS (Nv / 16)           /* 2048 */
#define TOT_BLKS (GEMM_BLKS + QZ_BLKS) /* 10240 = 5*2048 */

#define SPITCH 136                      /* fp16 per smem row per K-stage */
#define STAGE_BYTES (128 * SPITCH * 2)  /* 34816 */
#define FSMEM (2 * STAGE_BYTES)         /* 69632: A half + B half */

#define PPITCH 516 /* floats per row-pair lane in s_rp */

// ---------------- device scratch (no allocations allowed) ----------------
__device__ float g_res[(size_t)Nv * Dv];      // residual          32 MB
__device__ float g_xn[(size_t)Nv * Dv];       // normalized rows   32 MB
__device__ uint4 g_xh4[(size_t)Nv * Dv / 8];  // fp16 normalized   16 MB
__device__ float g_part[(size_t)Kv * NBN];    // sum-exp partials   4 MB
__device__ float g_lo[Kv];
__device__ float g_cbT[NQv * Dv * NEv];
__device__ float g_e2[NQv * NEv];
__device__ float g_r2[Nv];
__device__ float g_ssepart[QZ_BLKS];
__device__ float g_vq[NQv];

__device__ __forceinline__ uint32_t smem_u32(const void* p) {
    uint32_t a;
    asm("{ .reg .u64 t; cvta.to.shared.u64 t, %1; cvt.u32.u64 %0, t; }" : "=r"(a) : "l"(p));
    return a;
}
__device__ __forceinline__ void ldsm_x4(uint32_t& r0, uint32_t& r1, uint32_t& r2, uint32_t& r3,
                                        uint32_t addr) {
    asm volatile("ldmatrix.sync.aligned.m8n8.x4.shared.b16 {%0,%1,%2,%3}, [%4];"
                 : "=r"(r0), "=r"(r1), "=r"(r2), "=r"(r3) : "r"(addr));
}
// f16 inputs, f16 accumulate
__device__ __forceinline__ void mma_f16(uint32_t* c, const uint32_t* a, const uint32_t* b) {
    asm volatile(
        "mma.sync.aligned.m16n8k16.row.col.f16.f16.f16.f16 "
        "{%0,%1}, {%2,%3,%4,%5}, {%6,%7}, {%0,%1};"
        : "+r"(c[0]), "+r"(c[1])
        : "r"(a[0]), "r"(a[1]), "r"(a[2]), "r"(a[3]), "r"(b[0]), "r"(b[1]));
}

// ---------------- init: residual = x ----------------
__global__ void k_copy(const float* __restrict__ x) {
    size_t i = ((size_t)blockIdx.x * 256 + threadIdx.x) * 4;
    *(float4*)&g_res[i] = *(const float4*)&x[i];
}

// ---------------- codebook transpose ----------------
__global__ void k_prep_cb(const float* __restrict__ cb) {
    __shared__ float t[32][33];
    int qb = blockIdx.z;
    int j0 = blockIdx.x * 32, d0 = blockIdx.y * 32;
    int tx = threadIdx.x & 31, ty = threadIdx.x >> 5;
    const float* src = cb + (size_t)qb * NEv * Dv;
    float* dst = g_cbT + (size_t)qb * Dv * NEv;
#pragma unroll
    for (int i = 0; i < 32; i += 8)
        t[ty + i][tx] = src[(size_t)(j0 + ty + i) * Dv + d0 + tx];
    __syncthreads();
#pragma unroll
    for (int i = 0; i < 32; i += 8)
        dst[(size_t)(d0 + ty + i) * NEv + j0 + tx] = t[tx][ty + i];
}

// ---------------- codebook squared norms ----------------
__global__ void k_e2(const float* __restrict__ cb) {
    int gw = blockIdx.x * 8 + (threadIdx.x >> 5);
    int lane = threadIdx.x & 31;
    const float* row = cb + (size_t)gw * Dv;
    float s = 0.f;
    for (int d = lane; d < Dv; d += 32) { float v = row[d]; s = fmaf(v, v, s); }
#pragma unroll
    for (int o = 16; o; o >>= 1) s += __shfl_down_sync(~0u, s, o);
    if (!lane) g_e2[gw] = s;
}

// ---------------- row norms + normalization (fp32 + fp16) ----------------
__global__ void k_rownorm() {
    int row = blockIdx.x * 8 + (threadIdx.x >> 5);
    int lane = threadIdx.x & 31;
    const float* r = g_res + (size_t)row * Dv;
    float4 a = *(const float4*)&r[lane * 4];
    float4 b = *(const float4*)&r[128 + lane * 4];
    float s = ((a.x * a.x + a.y * a.y) + (a.z * a.z + a.w * a.w)) +
              ((b.x * b.x + b.y * b.y) + (b.z * b.z + b.w * b.w));
#pragma unroll
    for (int o = 16; o; o >>= 1) s += __shfl_down_sync(~0u, s, o);
    s = __shfl_sync(~0u, s, 0);
    if (!lane) g_r2[row] = s;
    float inv = rsqrtf(s + EPSv);
    float4 an = make_float4(a.x * inv, a.y * inv, a.z * inv, a.w * inv);
    float4 bn = make_float4(b.x * inv, b.y * inv, b.z * inv, b.w * inv);
    *(float4*)&g_xn[(size_t)row * Dv + lane * 4] = an;
    *(float4*)&g_xn[(size_t)row * Dv + 128 + lane * 4] = bn;
    __half2* xh = (__half2*)g_xh4;
    size_t hbase = (size_t)row * (Dv / 2);
    xh[hbase + lane * 2 + 0] = __floats2half2_rn(an.x, an.y);
    xh[hbase + lane * 2 + 1] = __floats2half2_rn(an.z, an.w);
    xh[hbase + 64 + lane * 2 + 0] = __floats2half2_rn(bn.x, bn.y);
    xh[hbase + 64 + lane * 2 + 1] = __floats2half2_rn(bn.z, bn.w);
}

// ============ fused heterogeneous kernel: GEMM tiles + quantize blocks ========
// Block types interleaved: every 5th block (b%5==4) is a quantize block so its
// FFMA work overlaps GEMM blocks' smem/tensor phases chip-wide.
__global__ void __launch_bounds__(256) k_fused(const float* __restrict__ cb, int qstep,
                                               const int* __restrict__ i1g,
                                               float* __restrict__ out_xq,
                                               float* __restrict__ out_idx) {
    extern __shared__ char smem[];
    int tid = threadIdx.x, lane = tid & 31, w = tid >> 5;
    int b = blockIdx.x;
    bool isq = (b % 5) == 4;

    if (!isq) {
        // ---------------- GEMM path ----------------
        int gid = b - b / 5;  // 0 .. GEMM_BLKS-1
        char* smA = smem;
        char* smB = smem + STAGE_BYTES;
        int wm = w >> 2, wn = w & 3;  // warp grid 2x4 (rows 64, cols 32)
        int bn = gid & (NBN - 1), bm = gid >> 8;

        const uint4* srcB = g_xh4 + (size_t)bn * BN * (Dv / 8);
        int qbase = bm * BM;

        uint32_t baseA = smem_u32(smA);
        uint32_t baseB = smem_u32(smB);
        uint32_t aAddr = baseA + ((wm * 64 + (lane & 15)) * SPITCH + (lane >> 4) * 8) * 2;
        uint32_t bAddr = baseB +
            ((wn * 32 + (lane & 7) + ((lane >> 4) & 1) * 8) * SPITCH) * 2 +
            ((lane >> 3) & 1) * 16;

        uint32_t acc[4][4][2];  // f16x2 accumulators
#pragma unroll
        for (int mt = 0; mt < 4; mt++)
#pragma unroll
            for (int nt = 0; nt < 4; nt++) { acc[mt][nt][0] = 0u; acc[mt][nt][1] = 0u; }

#pragma unroll
        for (int s = 0; s < 2; s++) {
            // stage K cols [s*128, s*128+128): A gathered via i1, B direct
#pragma unroll
            for (int i = 0; i < 8; i++) {
                int c = i * 256 + tid;
                int row = c >> 4, col = c & 15;
                uint32_t off = (uint32_t)(row * (SPITCH * 2) + col * 16);
                int qrow = i1g[qbase + row];
                *(uint4*)(smA + off) = g_xh4[(size_t)qrow * 32 + s * 16 + col];
                *(uint4*)(smB + off) = srcB[row * 32 + s * 16 + col];
            }
            __syncthreads();
#pragma unroll
            for (int ks = 0; ks < 8; ks++) {
                uint32_t a[4][4], bb[4][2];
                uint32_t ka = aAddr + ks * 32;
                uint32_t kb = bAddr + ks * 32;
#pragma unroll
                for (int mt = 0; mt < 4; mt++)
                    ldsm_x4(a[mt][0], a[mt][1], a[mt][2], a[mt][3],
                            ka + mt * 16 * SPITCH * 2);
#pragma unroll
                for (int nt2 = 0; nt2 < 2; nt2++)
                    ldsm_x4(bb[nt2 * 2][0], bb[nt2 * 2][1], bb[nt2 * 2 + 1][0],
                            bb[nt2 * 2 + 1][1], kb + nt2 * 16 * SPITCH * 2);
#pragma unroll
                for (int mt = 0; mt < 4; mt++)
#pragma unroll
                    for (int nt = 0; nt < 4; nt++)
                        mma_f16(acc[mt][nt], a[mt], bb[nt]);
            }
            __syncthreads();
        }

        // epilogue: exp row-sums. c0 = row lane/4, c1 = row lane/4+8.
        float sum_lo[4], sum_hi[4];
#pragma unroll
        for (int mt = 0; mt < 4; mt++) {
            float lo = 0.f, hi = 0.f;
#pragma unroll
            for (int nt = 0; nt < 4; nt++) {
                float2 p0 = __half22float2(*(__half2*)&acc[mt][nt][0]);
                float2 p1 = __half22float2(*(__half2*)&acc[mt][nt][1]);
                lo += __expf(p0.x * TEMP_INV) + __expf(p0.y * TEMP_INV);
                hi += __expf(p1.x * TEMP_INV) + __expf(p1.y * TEMP_INV);
            }
#pragma unroll
            for (int o = 1; o < 4; o <<= 1) {
                lo += __shfl_xor_sync(~0u, lo, o);
                hi += __shfl_xor_sync(~0u, hi, o);
            }
            sum_lo[mt] = lo;
            sum_hi[mt] = hi;
        }
        float* red = (float*)smem;  // [128][4], reuse post-sync
        if ((lane & 3) == 0) {
            int rb = wm * 64 + (lane >> 2);
#pragma unroll
            for (int mt = 0; mt < 4; mt++) {
                red[(rb + mt * 16) * 4 + wn] = sum_lo[mt];
                red[(rb + mt * 16 + 8) * 4 + wn] = sum_hi[mt];
            }
        }
        __syncthreads();
        if (tid < BM) {
            float s = (red[tid * 4 + 0] + red[tid * 4 + 1]) +
                      (red[tid * 4 + 2] + red[tid * 4 + 3]);
            g_part[(size_t)(bm * BM + tid) * NBN + bn] = s;
        }
        return;
    }

    // ---------------- quantize path (f32x2, two rows per lane-pair) ----------
    float* s_rp = (float*)smem;                      // 8 * 516 floats ~16.5 KB
    float* s_r2 = s_rp + 8 * PPITCH;                 // 16
    float* s_wminf = s_r2 + 16;                      // 16*8
    int* s_widx = (int*)(s_wminf + 16 * 8);          // 16*8
    int* s_idx = s_widx + 16 * 8;                    // 16
    float* s_red = (float*)(s_idx + 16);             // 256
    int qblk = b / 5;
    int r0 = qblk * 16;

    // load 16 rows pair-interleaved: s_rp[p*PPITCH + d*2 + j] = res[2p+j][d]
    {
        int r = tid & 15;
        int p = r >> 1, j = r & 1;
        float* dst = &s_rp[p * PPITCH + j];
#pragma unroll
        for (int i = 0; i < 4; i++) {
            int c = (tid >> 4) + i * 16;  // float4 index 0..63
            float4 v = *(const float4*)&g_res[(size_t)(r0 + r) * Dv + c * 4];
            dst[(c * 4 + 0) * 2] = v.x;
            dst[(c * 4 + 1) * 2] = v.y;
            dst[(c * 4 + 2) * 2] = v.z;
            dst[(c * 4 + 3) * 2] = v.w;
        }
    }
    if (tid < 16) s_r2[tid] = g_r2[r0 + tid];
    __syncthreads();

    // dot[2p+j] for codebook entry tid; two rows per fma.rn.f32x2
    const float* cT = g_cbT + (size_t)qstep * Dv * NEv;  // [d][j]
    unsigned long long acc2[8];
#pragma unroll
    for (int p = 0; p < 8; p++) acc2[p] = 0ull;
#pragma unroll 4
    for (int d = 0; d < Dv; d += 4) {
        float c0 = cT[(size_t)(d + 0) * NEv + tid];
        float c1 = cT[(size_t)(d + 1) * NEv + tid];
        float c2 = cT[(size_t)(d + 2) * NEv + tid];
        float c3 = cT[(size_t)(d + 3) * NEv + tid];
        unsigned long long b0, b1, b2, b3;
        asm("mov.b64 %0, {%1,%1};" : "=l"(b0) : "r"(__float_as_uint(c0)));
        asm("mov.b64 %0, {%1,%1};" : "=l"(b1) : "r"(__float_as_uint(c1)));
        asm("mov.b64 %0, {%1,%1};" : "=l"(b2) : "r"(__float_as_uint(c2)));
        asm("mov.b64 %0, {%1,%1};" : "=l"(b3) : "r"(__float_as_uint(c3)));
#pragma unroll
        for (int p = 0; p < 8; p++) {
            ulonglong2 v = *(const ulonglong2*)&s_rp[p * PPITCH + d * 2];
            ulonglong2 v2 = *(const ulonglong2*)&s_rp[p * PPITCH + d * 2 + 4];
            asm("fma.rn.f32x2 %0, %1, %2, %0;" : "+l"(acc2[p]) : "l"(v.x), "l"(b0));
            asm("fma.rn.f32x2 %0, %1, %2, %0;" : "+l"(acc2[p]) : "l"(v.y), "l"(b1));
            asm("fma.rn.f32x2 %0, %1, %2, %0;" : "+l"(acc2[p]) : "l"(v2.x), "l"(b2));
            asm("fma.rn.f32x2 %0, %1, %2, %0;" : "+l"(acc2[p]) : "l"(v2.y), "l"(b3));
        }
    }
    float e2v = g_e2[qstep * NEv + tid];
#pragma unroll
    for (int p = 0; p < 8; p++) {
        uint32_t ulo, uhi;
        asm("mov.b64 {%0,%1}, %2;" : "=r"(ulo), "=r"(uhi) : "l"(acc2[p]));
#pragma unroll
        for (int j = 0; j < 2; j++) {
            int r = 2 * p + j;
            float dot = __uint_as_float(j ? uhi : ulo);
            // reference rounding: (r2 - 2*dot) + e2, no contraction
            float d2 = __fadd_rn(__fadd_rn(s_r2[r], -__fmul_rn(2.0f, dot)), e2v);
            float mv = d2;
            int mi = tid;
#pragma unroll
            for (int o = 16; o; o >>= 1) {
                float ov = __shfl_down_sync(~0u, mv, o);
                int oi = __shfl_down_sync(~0u, mi, o);
                if (ov < mv || (ov == mv && oi < mi)) { mv = ov; mi = oi; }
            }
            if (!lane) { s_wminf[r * 8 + w] = mv; s_widx[r * 8 + w] = mi; }
        }
    }
    __syncthreads();
    if (tid < 16) {
        float mv = s_wminf[tid * 8 + 0];
        int mi = s_widx[tid * 8 + 0];
#pragma unroll
        for (int w2 = 1; w2 < 8; w2++) {
            float ov = s_wminf[tid * 8 + w2];
            int oi = s_widx[tid * 8 + w2];
            if (ov < mv || (ov == mv && oi < mi)) { mv = ov; mi = oi; }
        }
        s_idx[tid] = mi;
    }
    __syncthreads();

    const float* cbq = cb + (size_t)qstep * NEv * Dv;
    float sse = 0.f;
#pragma unroll
    for (int r = 0; r < 16; r++) {
        int row = r0 + r;
        int ci = s_idx[r];
        float e = cbq[(size_t)ci * Dv + tid];
        float rv = s_rp[(r >> 1) * PPITCH + tid * 2 + (r & 1)];
        float diff = __fsub_rn(e, rv);   // q - r
        sse = fmaf(diff, diff, sse);
        float xres = __fadd_rn(rv, diff);  // straight-through rounding
        g_res[(size_t)row * Dv + tid] = __fsub_rn(rv, xres);
        size_t oo = (size_t)row * Dv + tid;
        if (qstep == 0) out_xq[oo] = xres; else out_xq[oo] += xres;
        if (tid == 0) out_idx[(size_t)row * NQv + qstep] = (float)ci;
    }
    s_red[tid] = sse;
    __syncthreads();
#pragma unroll
    for (int o = 128; o; o >>= 1) {
        if (tid < o) s_red[tid] += s_red[tid + o];
        __syncthreads();
    }
    if (!tid) g_ssepart[qblk] = s_red[0];
}

// ---------------- lse per query (pos computed inline) ----------------
__global__ void k_lse(const int* __restrict__ i1, const int* __restrict__ i2) {
    int k = blockIdx.x * 8 + (threadIdx.x >> 5);
    int lane = threadIdx.x & 31;
    const float* x1 = g_xn + (size_t)i1[k] * Dv;
    const float* x2 = g_xn + (size_t)i2[k] * Dv;
    float4 a1 = *(const float4*)&x1[lane * 4];
    float4 b1 = *(const float4*)&x1[128 + lane * 4];
    float4 a2 = *(const float4*)&x2[lane * 4];
    float4 b2 = *(const float4*)&x2[128 + lane * 4];
    float ps = ((a1.x * a2.x + a1.y * a2.y) + (a1.z * a2.z + a1.w * a2.w)) +
               ((b1.x * b2.x + b1.y * b2.y) + (b1.z * b2.z + b1.w * b2.w));
#pragma unroll
    for (int o = 16; o; o >>= 1) ps += __shfl_down_sync(~0u, ps, o);

    const float* p = g_part + (size_t)k * NBN;
    double s = 0.0;
#pragma unroll
    for (int i = lane; i < NBN; i += 32) s += (double)p[i];
#pragma unroll
    for (int o = 16; o; o >>= 1) s += __shfl_down_sync(~0u, s, o);
    if (!lane) g_lo[k] = (float)log(s) - ps * TEMP_INV;
}

// ---------------- merged tail: block0 = outer mean, block1 = vq reduce -------
__global__ void k_tail(float* out_ol, int q) {
    __shared__ double red[256];
    int t = threadIdx.x;
    if (blockIdx.x == 0) {
        double s = 0.0;
        for (int i = t; i < Kv; i += 256) s += (double)g_lo[i];
        red[t] = s;
        __syncthreads();
#pragma unroll
        for (int o = 128; o; o >>= 1) {
            if (t < o) red[t] += red[t + o];
            __syncthreads();
        }
        if (!t) out_ol[q] = (float)(red[0] / (double)Kv);
    } else {
        double s = 0.0;
        for (int i = t; i < QZ_BLKS; i += 256) s += (double)g_ssepart[i];
        red[t] = s;
        __syncthreads();
#pragma unroll
        for (int o = 128; o; o >>= 1) {
            if (t < o) red[t] += red[t + o];
            __syncthreads();
        }
        if (!t) {
            float m = (float)(red[0] / ((double)Nv * (double)Dv));
            g_vq[q] = __fadd_rn(m, __fmul_rn(BETAv, m));
        }
    }
}

__global__ void k_final(float* out_ml) {
    if (threadIdx.x == 0)
        out_ml[0] = ((g_vq[0] + g_vq[1]) + (g_vq[2] + g_vq[3])) * 0.25f;
}

// ---------------- launch ----------------
extern "C" void kernel_launch(void* const* d_in, const int* in_sizes, int n_in,
                              void* d_out, int out_size) {
    const float* x = (const float*)d_in[0];
    const float* cb = (const float*)d_in[1];
    const int* i1 = (const int*)d_in[2];
    const int* i2 = (const int*)d_in[3];
    float* out = (float*)d_out;
    float* out_xq = out;
    float* out_ml = out + (size_t)Nv * Dv;
    float* out_ol = out_ml + 1;
    float* out_idx = out_ol + NQv;

    cudaFuncSetAttribute(k_fused, cudaFuncAttributeMaxDynamicSharedMemorySize, FSMEM);

    k_copy<<<(Nv * Dv) / 1024, 256>>>(x);
    k_prep_cb<<<dim3(NEv / 32, Dv / 32, NQv), 256>>>(cb);
    k_e2<<<(NQv * NEv) / 8, 256>>>(cb);

    for (int q = 0; q < NQv; q++) {
        k_rownorm<<<Nv / 8, 256>>>();
        k_fused<<<TOT_BLKS, 256, FSMEM>>>(cb, q, i1, out_xq, out_idx);
        k_lse<<<Kv / 8, 256>>>(i1, i2);
        k_tail<<<2, 256>>>(out_ol, q);
    }
    k_final<<<1, 1>>>(out_ml);
}